// round 2
// baseline (speedup 1.0000x reference)
#include <cuda_runtime.h>
#include <math.h>

#define BB 4
#define TT 2048
#define DD 1024
#define DK 128
#define RR (BB*TT)   // 8192

// Scratch (device globals: allocation-free)
__device__ float g_Q[RR*DK];
__device__ float g_K[RR*DK];
__device__ float g_V[RR*DK];
__device__ float g_O[RR*DK];

// ---------------------------------------------------------------------------
// Generic SGEMM: C[M,N] = A[M,K] @ B[K,N], row-major, all dims multiples of
// tile sizes (M%64==0, N%128==0, K%16==0). 256 threads, 4x8 register tile.
// ---------------------------------------------------------------------------
__global__ __launch_bounds__(256) void gemm_kernel(
    const float* __restrict__ A, const float* __restrict__ Bw,
    float* __restrict__ C, int M, int N, int K)
{
    __shared__ float As[64*16];
    __shared__ float Bs[16*128];
    const int tid = threadIdx.x;
    const int tx = tid & 15, ty = tid >> 4;
    const int m0 = blockIdx.y * 64;
    const int n0 = blockIdx.x * 128;

    float acc[4][8];
#pragma unroll
    for (int r = 0; r < 4; r++)
#pragma unroll
        for (int j = 0; j < 8; j++) acc[r][j] = 0.f;

    for (int k0 = 0; k0 < K; k0 += 16) {
#pragma unroll
        for (int i = 0; i < 4; i++) {          // A tile: 64x16
            int e = tid * 4 + i;
            int r = e >> 4, kk = e & 15;
            As[e] = A[(size_t)(m0 + r) * K + k0 + kk];
        }
#pragma unroll
        for (int i = 0; i < 8; i++) {          // B tile: 16x128
            int e = tid * 8 + i;
            int kk = e >> 7, n = e & 127;
            Bs[e] = Bw[(size_t)(k0 + kk) * N + n0 + n];
        }
        __syncthreads();
#pragma unroll
        for (int kk = 0; kk < 16; kk++) {
            float a[4], b[8];
#pragma unroll
            for (int r = 0; r < 4; r++) a[r] = As[(ty * 4 + r) * 16 + kk];
#pragma unroll
            for (int j = 0; j < 8; j++) b[j] = Bs[kk * 128 + j * 16 + tx];
#pragma unroll
            for (int r = 0; r < 4; r++)
#pragma unroll
                for (int j = 0; j < 8; j++) acc[r][j] += a[r] * b[j];
        }
        __syncthreads();
    }
#pragma unroll
    for (int r = 0; r < 4; r++)
#pragma unroll
        for (int j = 0; j < 8; j++)
            C[(size_t)(m0 + ty * 4 + r) * N + n0 + j * 16 + tx] = acc[r][j];
}

// ---------------------------------------------------------------------------
// Flash attention (causal), BQ=64 rows per block, BKV=64, d=128.
// Grid: (T/64, B). 256 threads as 16x16. Thread tile: 4 rows x (4 S-cols,
// 8 O-cols). K held transposed in smem (stride 68, 16B aligned rows) for
// conflict-free LDS.128 in the S phase. Online softmax across the 16-lane
// row group via shfl_xor.
// ---------------------------------------------------------------------------
#define KT_STRIDE 68
#define FLASH_SMEM_FLOATS (64*128 + 128*KT_STRIDE + 64*128 + 64*64)

__global__ __launch_bounds__(256) void flash_kernel()
{
    extern __shared__ float sm[];
    float* Qs = sm;                         // 64*128
    float* Kt = Qs + 64 * 128;              // 128*68 (K transposed: Kt[d][c])
    float* Vs = Kt + 128 * KT_STRIDE;       // 64*128
    float* Ps = Vs + 64 * 128;              // 64*64

    const int tid = threadIdx.x;
    const int tx = tid & 15, ty = tid >> 4;
    const int qt = blockIdx.x;              // query tile index (0..31)
    const int b  = blockIdx.y;
    const int q0 = qt * 64;

    const float* Qg = g_Q + (size_t)(b * TT + q0) * DK;
    const float* Kg = g_K + (size_t)b * TT * DK;
    const float* Vg = g_V + (size_t)b * TT * DK;

    // Load Q tile (coalesced)
#pragma unroll
    for (int i = 0; i < 32; i++) {
        int e = i * 256 + tid;
        Qs[e] = Qg[e];
    }

    float m[4], l[4], acc[4][8];
#pragma unroll
    for (int r = 0; r < 4; r++) { m[r] = -1e30f; l[r] = 0.f; }
#pragma unroll
    for (int r = 0; r < 4; r++)
#pragma unroll
        for (int j = 0; j < 8; j++) acc[r][j] = 0.f;

    const float scale = 0.08838834764831845f;   // 1/sqrt(128)

    for (int j = 0; j <= qt; j++) {
        __syncthreads();   // prev iter's Ps/Vs/Kt reads done (also covers Qs load)

        // Load K tile transposed + V tile straight
        const float* Kj = Kg + (size_t)j * 64 * DK;
        const float* Vj = Vg + (size_t)j * 64 * DK;
#pragma unroll
        for (int i = 0; i < 32; i++) {
            int e = i * 256 + tid;
            int c = e >> 7, d = e & 127;
            Kt[d * KT_STRIDE + c] = Kj[e];
            Vs[e] = Vj[e];
        }
        __syncthreads();

        // --- S = Q K^T (4x4 per thread) ---
        float S[4][4];
#pragma unroll
        for (int r = 0; r < 4; r++)
#pragma unroll
            for (int cc = 0; cc < 4; cc++) S[r][cc] = 0.f;

        for (int d0 = 0; d0 < 128; d0 += 4) {
            float4 kv[4];
#pragma unroll
            for (int t = 0; t < 4; t++)
                kv[t] = *(const float4*)&Kt[(d0 + t) * KT_STRIDE + tx * 4];
#pragma unroll
            for (int r = 0; r < 4; r++) {
                float4 q4 = *(const float4*)&Qs[(ty * 4 + r) * 128 + d0];
                S[r][0] += q4.x*kv[0].x + q4.y*kv[1].x + q4.z*kv[2].x + q4.w*kv[3].x;
                S[r][1] += q4.x*kv[0].y + q4.y*kv[1].y + q4.z*kv[2].y + q4.w*kv[3].y;
                S[r][2] += q4.x*kv[0].z + q4.y*kv[1].z + q4.z*kv[2].z + q4.w*kv[3].z;
                S[r][3] += q4.x*kv[0].w + q4.y*kv[1].w + q4.z*kv[2].w + q4.w*kv[3].w;
            }
        }

        // scale + causal mask (only the diagonal tile needs it)
#pragma unroll
        for (int r = 0; r < 4; r++)
#pragma unroll
            for (int cc = 0; cc < 4; cc++) S[r][cc] *= scale;
        if (j == qt) {
#pragma unroll
            for (int r = 0; r < 4; r++) {
                int row = q0 + ty * 4 + r;
#pragma unroll
                for (int cc = 0; cc < 4; cc++) {
                    int col = j * 64 + tx * 4 + cc;
                    if (col > row) S[r][cc] = -1e30f;
                }
            }
        }

        // --- online softmax, P -> smem ---
#pragma unroll
        for (int r = 0; r < 4; r++) {
            float mt = fmaxf(fmaxf(S[r][0], S[r][1]), fmaxf(S[r][2], S[r][3]));
#pragma unroll
            for (int off = 1; off < 16; off <<= 1)
                mt = fmaxf(mt, __shfl_xor_sync(0xffffffffu, mt, off));
            float mn = fmaxf(m[r], mt);
            float alpha = __expf(m[r] - mn);
            float p0 = __expf(S[r][0] - mn);
            float p1 = __expf(S[r][1] - mn);
            float p2 = __expf(S[r][2] - mn);
            float p3 = __expf(S[r][3] - mn);
            float lt = (p0 + p1) + (p2 + p3);
#pragma unroll
            for (int off = 1; off < 16; off <<= 1)
                lt += __shfl_xor_sync(0xffffffffu, lt, off);
            l[r] = l[r] * alpha + lt;
            m[r] = mn;
#pragma unroll
            for (int jj = 0; jj < 8; jj++) acc[r][jj] *= alpha;
            float* pr = &Ps[(ty * 4 + r) * 64 + tx * 4];
            pr[0] = p0; pr[1] = p1; pr[2] = p2; pr[3] = p3;
        }
        __syncthreads();

        // --- O += P V ---
        for (int c = 0; c < 64; c++) {
            float p[4], v[8];
#pragma unroll
            for (int r = 0; r < 4; r++) p[r] = Ps[(ty * 4 + r) * 64 + c];
#pragma unroll
            for (int jj = 0; jj < 8; jj++) v[jj] = Vs[c * 128 + jj * 16 + tx];
#pragma unroll
            for (int r = 0; r < 4; r++)
#pragma unroll
                for (int jj = 0; jj < 8; jj++) acc[r][jj] += p[r] * v[jj];
        }
    }

    // epilogue: normalize and store O
#pragma unroll
    for (int r = 0; r < 4; r++) {
        float inv = 1.f / l[r];
        int row = b * TT + q0 + ty * 4 + r;
#pragma unroll
        for (int jj = 0; jj < 8; jj++)
            g_O[(size_t)row * DK + jj * 16 + tx] = acc[r][jj] * inv;
    }
}

// ---------------------------------------------------------------------------
extern "C" void kernel_launch(void* const* d_in, const int* in_sizes, int n_in,
                              void* d_out, int out_size)
{
    const float* x  = (const float*)d_in[0];
    const float* Wq = (const float*)d_in[1];
    const float* Wk = (const float*)d_in[2];
    const float* Wv = (const float*)d_in[3];
    const float* Wo = (const float*)d_in[4];
    float* out = (float*)d_out;

    float *gq, *gk, *gv, *go;
    cudaGetSymbolAddress((void**)&gq, g_Q);
    cudaGetSymbolAddress((void**)&gk, g_K);
    cudaGetSymbolAddress((void**)&gv, g_V);
    cudaGetSymbolAddress((void**)&go, g_O);

    const int flash_smem = FLASH_SMEM_FLOATS * (int)sizeof(float);  // 116736 B
    cudaFuncSetAttribute(flash_kernel,
                         cudaFuncAttributeMaxDynamicSharedMemorySize, flash_smem);

    dim3 blk(256);
    // Q/K/V projections: [8192,1024] @ [1024,128]
    gemm_kernel<<<dim3(1, RR / 64), blk>>>(x, Wq, gq, RR, DK, DD);
    gemm_kernel<<<dim3(1, RR / 64), blk>>>(x, Wk, gk, RR, DK, DD);
    gemm_kernel<<<dim3(1, RR / 64), blk>>>(x, Wv, gv, RR, DK, DD);

    // Causal flash attention
    flash_kernel<<<dim3(TT / 64, BB), blk, flash_smem>>>();

    // Output projection: [8192,128] @ [128,1024]
    gemm_kernel<<<dim3(DD / 128, RR / 64), blk>>>(go, Wo, out, RR, DD, DK);
}

// round 3
// speedup vs baseline: 1.0033x; 1.0033x over previous
#include <cuda_runtime.h>
#include <math.h>

#define BB 4
#define TT 2048
#define DD 1024
#define DK 128
#define RR (BB*TT)   // 8192

// Scratch (device globals: allocation-free)
__device__ float g_Q[RR*DK];
__device__ float g_K[RR*DK];
__device__ float g_V[RR*DK];
__device__ float g_O[RR*DK];

// ---------------------------------------------------------------------------
// Generic SGEMM: C[M,N] = A[M,K] @ B[K,N], row-major, all dims multiples of
// tile sizes (M%64==0, N%128==0, K%16==0). 256 threads, 4x8 register tile.
// ---------------------------------------------------------------------------
__global__ __launch_bounds__(256) void gemm_kernel(
    const float* __restrict__ A, const float* __restrict__ Bw,
    float* __restrict__ C, int M, int N, int K)
{
    __shared__ float As[64*16];
    __shared__ float Bs[16*128];
    const int tid = threadIdx.x;
    const int tx = tid & 15, ty = tid >> 4;
    const int m0 = blockIdx.y * 64;
    const int n0 = blockIdx.x * 128;

    float acc[4][8];
#pragma unroll
    for (int r = 0; r < 4; r++)
#pragma unroll
        for (int j = 0; j < 8; j++) acc[r][j] = 0.f;

    for (int k0 = 0; k0 < K; k0 += 16) {
#pragma unroll
        for (int i = 0; i < 4; i++) {          // A tile: 64x16
            int e = tid * 4 + i;
            int r = e >> 4, kk = e & 15;
            As[e] = A[(size_t)(m0 + r) * K + k0 + kk];
        }
#pragma unroll
        for (int i = 0; i < 8; i++) {          // B tile: 16x128
            int e = tid * 8 + i;
            int kk = e >> 7, n = e & 127;
            Bs[e] = Bw[(size_t)(k0 + kk) * N + n0 + n];
        }
        __syncthreads();
#pragma unroll
        for (int kk = 0; kk < 16; kk++) {
            float a[4], b[8];
#pragma unroll
            for (int r = 0; r < 4; r++) a[r] = As[(ty * 4 + r) * 16 + kk];
#pragma unroll
            for (int j = 0; j < 8; j++) b[j] = Bs[kk * 128 + j * 16 + tx];
#pragma unroll
            for (int r = 0; r < 4; r++)
#pragma unroll
                for (int j = 0; j < 8; j++) acc[r][j] += a[r] * b[j];
        }
        __syncthreads();
    }
#pragma unroll
    for (int r = 0; r < 4; r++)
#pragma unroll
        for (int j = 0; j < 8; j++)
            C[(size_t)(m0 + ty * 4 + r) * N + n0 + j * 16 + tx] = acc[r][j];
}

// ---------------------------------------------------------------------------
// Flash attention (causal), BQ=64 rows per block, BKV=64, d=128.
// Grid: (T/64, B). 256 threads as 16x16. Thread tile: 4 rows x (4 S-cols,
// 8 O-cols). K held transposed in smem (stride 68, 16B aligned rows) for
// conflict-free LDS.128 in the S phase. Online softmax across the 16-lane
// row group via shfl_xor.
// ---------------------------------------------------------------------------
#define KT_STRIDE 68
#define FLASH_SMEM_FLOATS (64*128 + 128*KT_STRIDE + 64*128 + 64*64)

__global__ __launch_bounds__(256) void flash_kernel()
{
    extern __shared__ float sm[];
    float* Qs = sm;                         // 64*128
    float* Kt = Qs + 64 * 128;              // 128*68 (K transposed: Kt[d][c])
    float* Vs = Kt + 128 * KT_STRIDE;       // 64*128
    float* Ps = Vs + 64 * 128;              // 64*64

    const int tid = threadIdx.x;
    const int tx = tid & 15, ty = tid >> 4;
    const int qt = blockIdx.x;              // query tile index (0..31)
    const int b  = blockIdx.y;
    const int q0 = qt * 64;

    const float* Qg = g_Q + (size_t)(b * TT + q0) * DK;
    const float* Kg = g_K + (size_t)b * TT * DK;
    const float* Vg = g_V + (size_t)b * TT * DK;

    // Load Q tile (coalesced)
#pragma unroll
    for (int i = 0; i < 32; i++) {
        int e = i * 256 + tid;
        Qs[e] = Qg[e];
    }

    float m[4], l[4], acc[4][8];
#pragma unroll
    for (int r = 0; r < 4; r++) { m[r] = -1e30f; l[r] = 0.f; }
#pragma unroll
    for (int r = 0; r < 4; r++)
#pragma unroll
        for (int j = 0; j < 8; j++) acc[r][j] = 0.f;

    const float scale = 0.08838834764831845f;   // 1/sqrt(128)

    for (int j = 0; j <= qt; j++) {
        __syncthreads();   // prev iter's Ps/Vs/Kt reads done (also covers Qs load)

        // Load K tile transposed + V tile straight
        const float* Kj = Kg + (size_t)j * 64 * DK;
        const float* Vj = Vg + (size_t)j * 64 * DK;
#pragma unroll
        for (int i = 0; i < 32; i++) {
            int e = i * 256 + tid;
            int c = e >> 7, d = e & 127;
            Kt[d * KT_STRIDE + c] = Kj[e];
            Vs[e] = Vj[e];
        }
        __syncthreads();

        // --- S = Q K^T (4x4 per thread) ---
        float S[4][4];
#pragma unroll
        for (int r = 0; r < 4; r++)
#pragma unroll
            for (int cc = 0; cc < 4; cc++) S[r][cc] = 0.f;

        for (int d0 = 0; d0 < 128; d0 += 4) {
            float4 kv[4];
#pragma unroll
            for (int t = 0; t < 4; t++)
                kv[t] = *(const float4*)&Kt[(d0 + t) * KT_STRIDE + tx * 4];
#pragma unroll
            for (int r = 0; r < 4; r++) {
                float4 q4 = *(const float4*)&Qs[(ty * 4 + r) * 128 + d0];
                S[r][0] += q4.x*kv[0].x + q4.y*kv[1].x + q4.z*kv[2].x + q4.w*kv[3].x;
                S[r][1] += q4.x*kv[0].y + q4.y*kv[1].y + q4.z*kv[2].y + q4.w*kv[3].y;
                S[r][2] += q4.x*kv[0].z + q4.y*kv[1].z + q4.z*kv[2].z + q4.w*kv[3].z;
                S[r][3] += q4.x*kv[0].w + q4.y*kv[1].w + q4.z*kv[2].w + q4.w*kv[3].w;
            }
        }

        // scale + causal mask (only the diagonal tile needs it)
#pragma unroll
        for (int r = 0; r < 4; r++)
#pragma unroll
            for (int cc = 0; cc < 4; cc++) S[r][cc] *= scale;
        if (j == qt) {
#pragma unroll
            for (int r = 0; r < 4; r++) {
                int row = q0 + ty * 4 + r;
#pragma unroll
                for (int cc = 0; cc < 4; cc++) {
                    int col = j * 64 + tx * 4 + cc;
                    if (col > row) S[r][cc] = -1e30f;
                }
            }
        }

        // --- online softmax, P -> smem ---
#pragma unroll
        for (int r = 0; r < 4; r++) {
            float mt = fmaxf(fmaxf(S[r][0], S[r][1]), fmaxf(S[r][2], S[r][3]));
#pragma unroll
            for (int off = 1; off < 16; off <<= 1)
                mt = fmaxf(mt, __shfl_xor_sync(0xffffffffu, mt, off));
            float mn = fmaxf(m[r], mt);
            float alpha = __expf(m[r] - mn);
            float p0 = __expf(S[r][0] - mn);
            float p1 = __expf(S[r][1] - mn);
            float p2 = __expf(S[r][2] - mn);
            float p3 = __expf(S[r][3] - mn);
            float lt = (p0 + p1) + (p2 + p3);
#pragma unroll
            for (int off = 1; off < 16; off <<= 1)
                lt += __shfl_xor_sync(0xffffffffu, lt, off);
            l[r] = l[r] * alpha + lt;
            m[r] = mn;
#pragma unroll
            for (int jj = 0; jj < 8; jj++) acc[r][jj] *= alpha;
            float* pr = &Ps[(ty * 4 + r) * 64 + tx * 4];
            pr[0] = p0; pr[1] = p1; pr[2] = p2; pr[3] = p3;
        }
        __syncthreads();

        // --- O += P V ---
        for (int c = 0; c < 64; c++) {
            float p[4], v[8];
#pragma unroll
            for (int r = 0; r < 4; r++) p[r] = Ps[(ty * 4 + r) * 64 + c];
#pragma unroll
            for (int jj = 0; jj < 8; jj++) v[jj] = Vs[c * 128 + jj * 16 + tx];
#pragma unroll
            for (int r = 0; r < 4; r++)
#pragma unroll
                for (int jj = 0; jj < 8; jj++) acc[r][jj] += p[r] * v[jj];
        }
    }

    // epilogue: normalize and store O
#pragma unroll
    for (int r = 0; r < 4; r++) {
        float inv = 1.f / l[r];
        int row = b * TT + q0 + ty * 4 + r;
#pragma unroll
        for (int jj = 0; jj < 8; jj++)
            g_O[(size_t)row * DK + jj * 16 + tx] = acc[r][jj] * inv;
    }
}

// ---------------------------------------------------------------------------
extern "C" void kernel_launch(void* const* d_in, const int* in_sizes, int n_in,
                              void* d_out, int out_size)
{
    const float* x  = (const float*)d_in[0];
    const float* Wq = (const float*)d_in[1];
    const float* Wk = (const float*)d_in[2];
    const float* Wv = (const float*)d_in[3];
    const float* Wo = (const float*)d_in[4];
    float* out = (float*)d_out;

    float *gq, *gk, *gv, *go;
    cudaGetSymbolAddress((void**)&gq, g_Q);
    cudaGetSymbolAddress((void**)&gk, g_K);
    cudaGetSymbolAddress((void**)&gv, g_V);
    cudaGetSymbolAddress((void**)&go, g_O);

    const int flash_smem = FLASH_SMEM_FLOATS * (int)sizeof(float);  // 116736 B
    cudaFuncSetAttribute(flash_kernel,
                         cudaFuncAttributeMaxDynamicSharedMemorySize, flash_smem);

    dim3 blk(256);
    // Q/K/V projections: [8192,1024] @ [1024,128]
    gemm_kernel<<<dim3(1, RR / 64), blk>>>(x, Wq, gq, RR, DK, DD);
    gemm_kernel<<<dim3(1, RR / 64), blk>>>(x, Wk, gk, RR, DK, DD);
    gemm_kernel<<<dim3(1, RR / 64), blk>>>(x, Wv, gv, RR, DK, DD);

    // Causal flash attention
    flash_kernel<<<dim3(TT / 64, BB), blk, flash_smem>>>();

    // Output projection: [8192,128] @ [128,1024]
    gemm_kernel<<<dim3(DD / 128, RR / 64), blk>>>(go, Wo, out, RR, DD, DK);
}

// round 4
// speedup vs baseline: 1.1243x; 1.1206x over previous
#include <cuda_runtime.h>
#include <math.h>

#define BB 4
#define TT 2048
#define DD 1024
#define DK 128
#define RR (BB*TT)   // 8192

// Scratch (device globals: allocation-free)
__device__ float g_Q[RR*DK];
__device__ float g_K[RR*DK];
__device__ float g_V[RR*DK];
__device__ float g_O[RR*DK];

// ---------------------------------------------------------------------------
// GEMM tile body: C[m0:m0+64, n0:n0+128] = A[M,K] @ B[K,N] (row-major).
// 256 threads, 4x8 register tile, BK=16, A stored transposed in smem.
// Inner loop: 3 LDS.128 per 32 FMA per thread.
// ---------------------------------------------------------------------------
#define AS_STRIDE 68

__device__ __forceinline__ void gemm_tile_64x128(
    const float* __restrict__ A, const float* __restrict__ Bw,
    float* __restrict__ C, int M, int N, int K, int m0, int n0)
{
    __shared__ float As[16 * AS_STRIDE];   // [kk][row], padded
    __shared__ float Bs[16 * 128];         // [kk][col]

    const int tid = threadIdx.x;
    const int tx = tid & 15, ty = tid >> 4;

    float acc[4][8];
#pragma unroll
    for (int r = 0; r < 4; r++)
#pragma unroll
        for (int j = 0; j < 8; j++) acc[r][j] = 0.f;

    // A tile load indices: 64 rows x 16 k = 256 float4
    const int ar = tid >> 2;                 // row 0..63
    const int akg = (tid & 3) * 4;           // k group 0,4,8,12

    for (int k0 = 0; k0 < K; k0 += 16) {
        // --- load A tile transposed ---
        float4 a = *(const float4*)&A[(size_t)(m0 + ar) * K + k0 + akg];
        As[(akg + 0) * AS_STRIDE + ar] = a.x;
        As[(akg + 1) * AS_STRIDE + ar] = a.y;
        As[(akg + 2) * AS_STRIDE + ar] = a.z;
        As[(akg + 3) * AS_STRIDE + ar] = a.w;
        // --- load B tile straight (16x128 = 512 float4, 2 per thread) ---
#pragma unroll
        for (int t = 0; t < 2; t++) {
            int idx = tid + t * 256;
            int br = idx >> 5, bc = (idx & 31) * 4;
            *(float4*)&Bs[br * 128 + bc] =
                *(const float4*)&Bw[(size_t)(k0 + br) * N + n0 + bc];
        }
        __syncthreads();

#pragma unroll
        for (int kk = 0; kk < 16; kk++) {
            float4 a4 = *(const float4*)&As[kk * AS_STRIDE + ty * 4];
            float4 b0 = *(const float4*)&Bs[kk * 128 + tx * 4];
            float4 b1 = *(const float4*)&Bs[kk * 128 + tx * 4 + 64];
            float av[4] = {a4.x, a4.y, a4.z, a4.w};
            float bv[8] = {b0.x, b0.y, b0.z, b0.w, b1.x, b1.y, b1.z, b1.w};
#pragma unroll
            for (int r = 0; r < 4; r++)
#pragma unroll
                for (int j = 0; j < 8; j++) acc[r][j] += av[r] * bv[j];
        }
        __syncthreads();
    }

#pragma unroll
    for (int r = 0; r < 4; r++) {
        size_t row = (size_t)(m0 + ty * 4 + r) * N + n0;
        float4 o0 = {acc[r][0], acc[r][1], acc[r][2], acc[r][3]};
        float4 o1 = {acc[r][4], acc[r][5], acc[r][6], acc[r][7]};
        *(float4*)&C[row + tx * 4]      = o0;
        *(float4*)&C[row + tx * 4 + 64] = o1;
    }
}

// Fused QKV projection: grid (128, 1, 3), blockIdx.z selects W / output.
__global__ __launch_bounds__(256) void qkv_kernel(
    const float* __restrict__ x,
    const float* __restrict__ Wq,
    const float* __restrict__ Wk,
    const float* __restrict__ Wv)
{
    const float* W;
    float* C;
    if (blockIdx.z == 0)      { W = Wq; C = g_Q; }
    else if (blockIdx.z == 1) { W = Wk; C = g_K; }
    else                      { W = Wv; C = g_V; }
    gemm_tile_64x128(x, W, C, RR, DK, DD, blockIdx.x * 64, 0);
}

// Output projection: grid (8, 128).
__global__ __launch_bounds__(256) void outproj_kernel(
    const float* __restrict__ Wo, float* __restrict__ out)
{
    gemm_tile_64x128(g_O, Wo, out, RR, DD, DK, blockIdx.y * 64, blockIdx.x * 128);
}

// ---------------------------------------------------------------------------
// Flash attention (causal), BQ=64, BKV=64, d=128, 512 threads.
// Thread layout: tx = tid&15 (S cols: tx*4..+3; O cols: tx*8..+7),
//                tyS = tid>>4 in [0,32) (rows: tyS*2 + {0,1}).
// Qs padded to stride 132, Kt (transposed K) stride 68, Ps stride 68.
// ---------------------------------------------------------------------------
#define QS_STRIDE 132
#define KT_STRIDE 68
#define PS_STRIDE 68
#define FLASH_SMEM_FLOATS (64*QS_STRIDE + 128*KT_STRIDE + 64*128 + 64*PS_STRIDE)

__global__ __launch_bounds__(512) void flash_kernel()
{
    extern __shared__ float sm[];
    float* Qs = sm;                          // 64 x 132
    float* Kt = Qs + 64 * QS_STRIDE;         // 128 x 68 (Kt[d][c])
    float* Vs = Kt + 128 * KT_STRIDE;        // 64 x 128
    float* Ps = Vs + 64 * 128;               // 64 x 68

    const int tid = threadIdx.x;
    const int tx = tid & 15;
    const int tyS = tid >> 4;                // 0..31
    const int row0 = tyS * 2;
    const int qt = blockIdx.x;
    const int b  = blockIdx.y;
    const int q0 = qt * 64;

    const float* Qg = g_Q + (size_t)(b * TT + q0) * DK;
    const float* Kg = g_K + (size_t)b * TT * DK;
    const float* Vg = g_V + (size_t)b * TT * DK;

    // Load Q tile (coalesced, padded stride)
#pragma unroll
    for (int i = 0; i < 16; i++) {
        int e = i * 512 + tid;
        Qs[(e >> 7) * QS_STRIDE + (e & 127)] = Qg[e];
    }

    float m[2], l[2], acc[2][8];
#pragma unroll
    for (int r = 0; r < 2; r++) { m[r] = -1e30f; l[r] = 0.f; }
#pragma unroll
    for (int r = 0; r < 2; r++)
#pragma unroll
        for (int j = 0; j < 8; j++) acc[r][j] = 0.f;

    const float scale = 0.08838834764831845f;   // 1/sqrt(128)

    // K transpose-load indices: c = tid&63, d block = (tid>>6)*16
    const int kc = tid & 63;
    const int kd0 = (tid >> 6) * 16;

    for (int j = 0; j <= qt; j++) {
        __syncthreads();   // prev iter's Kt/Vs reads complete

        const float* Kj = Kg + (size_t)j * 64 * DK;
        const float* Vj = Vg + (size_t)j * 64 * DK;
        // K transposed: thread reads 64B contiguous of row kc, scatters
        // conflict-free (banks = c within warp).
#pragma unroll
        for (int t = 0; t < 4; t++) {
            float4 kf = *(const float4*)&Kj[(size_t)kc * DK + kd0 + t * 4];
            int d = kd0 + t * 4;
            Kt[(d + 0) * KT_STRIDE + kc] = kf.x;
            Kt[(d + 1) * KT_STRIDE + kc] = kf.y;
            Kt[(d + 2) * KT_STRIDE + kc] = kf.z;
            Kt[(d + 3) * KT_STRIDE + kc] = kf.w;
        }
        // V straight (coalesced)
#pragma unroll
        for (int i = 0; i < 16; i++) {
            int e = i * 512 + tid;
            Vs[e] = Vj[e];
        }
        __syncthreads();

        // --- S = Q K^T (2 rows x 4 cols per thread) ---
        float S[2][4];
#pragma unroll
        for (int r = 0; r < 2; r++)
#pragma unroll
            for (int cc = 0; cc < 4; cc++) S[r][cc] = 0.f;

#pragma unroll 4
        for (int d0 = 0; d0 < 128; d0 += 4) {
            float4 kv[4];
#pragma unroll
            for (int t = 0; t < 4; t++)
                kv[t] = *(const float4*)&Kt[(d0 + t) * KT_STRIDE + tx * 4];
#pragma unroll
            for (int r = 0; r < 2; r++) {
                float4 q4 = *(const float4*)&Qs[(row0 + r) * QS_STRIDE + d0];
                S[r][0] += q4.x*kv[0].x + q4.y*kv[1].x + q4.z*kv[2].x + q4.w*kv[3].x;
                S[r][1] += q4.x*kv[0].y + q4.y*kv[1].y + q4.z*kv[2].y + q4.w*kv[3].y;
                S[r][2] += q4.x*kv[0].z + q4.y*kv[1].z + q4.z*kv[2].z + q4.w*kv[3].z;
                S[r][3] += q4.x*kv[0].w + q4.y*kv[1].w + q4.z*kv[2].w + q4.w*kv[3].w;
            }
        }

#pragma unroll
        for (int r = 0; r < 2; r++)
#pragma unroll
            for (int cc = 0; cc < 4; cc++) S[r][cc] *= scale;

        if (j == qt) {   // causal mask only on diagonal tile
#pragma unroll
            for (int r = 0; r < 2; r++) {
                int row = q0 + row0 + r;
#pragma unroll
                for (int cc = 0; cc < 4; cc++) {
                    int col = j * 64 + tx * 4 + cc;
                    if (col > row) S[r][cc] = -1e30f;
                }
            }
        }

        // --- online softmax (row spread over 16 tx lanes) ---
#pragma unroll
        for (int r = 0; r < 2; r++) {
            float mt = fmaxf(fmaxf(S[r][0], S[r][1]), fmaxf(S[r][2], S[r][3]));
#pragma unroll
            for (int off = 1; off < 16; off <<= 1)
                mt = fmaxf(mt, __shfl_xor_sync(0xffffffffu, mt, off));
            float mn = fmaxf(m[r], mt);
            float alpha = __expf(m[r] - mn);
            float p0 = __expf(S[r][0] - mn);
            float p1 = __expf(S[r][1] - mn);
            float p2 = __expf(S[r][2] - mn);
            float p3 = __expf(S[r][3] - mn);
            float lt = (p0 + p1) + (p2 + p3);
#pragma unroll
            for (int off = 1; off < 16; off <<= 1)
                lt += __shfl_xor_sync(0xffffffffu, lt, off);
            l[r] = l[r] * alpha + lt;
            m[r] = mn;
#pragma unroll
            for (int jj = 0; jj < 8; jj++) acc[r][jj] *= alpha;
            float4 pv = {p0, p1, p2, p3};
            *(float4*)&Ps[(row0 + r) * PS_STRIDE + tx * 4] = pv;
        }
        __syncwarp();   // Ps producer/consumer are the same half-warp

        // --- O += P V (float4 V loads, cols tx*8..+7) ---
#pragma unroll 4
        for (int c = 0; c < 64; c++) {
            float p0 = Ps[(row0 + 0) * PS_STRIDE + c];
            float p1 = Ps[(row0 + 1) * PS_STRIDE + c];
            float4 v0 = *(const float4*)&Vs[c * 128 + tx * 8];
            float4 v1 = *(const float4*)&Vs[c * 128 + tx * 8 + 4];
            acc[0][0] += p0 * v0.x; acc[0][1] += p0 * v0.y;
            acc[0][2] += p0 * v0.z; acc[0][3] += p0 * v0.w;
            acc[0][4] += p0 * v1.x; acc[0][5] += p0 * v1.y;
            acc[0][6] += p0 * v1.z; acc[0][7] += p0 * v1.w;
            acc[1][0] += p1 * v0.x; acc[1][1] += p1 * v0.y;
            acc[1][2] += p1 * v0.z; acc[1][3] += p1 * v0.w;
            acc[1][4] += p1 * v1.x; acc[1][5] += p1 * v1.y;
            acc[1][6] += p1 * v1.z; acc[1][7] += p1 * v1.w;
        }
    }

    // epilogue: normalize and store O (float4)
#pragma unroll
    for (int r = 0; r < 2; r++) {
        float inv = 1.f / l[r];
        size_t row = (size_t)(b * TT + q0 + row0 + r) * DK;
        float4 o0 = {acc[r][0]*inv, acc[r][1]*inv, acc[r][2]*inv, acc[r][3]*inv};
        float4 o1 = {acc[r][4]*inv, acc[r][5]*inv, acc[r][6]*inv, acc[r][7]*inv};
        *(float4*)&g_O[row + tx * 8]     = o0;
        *(float4*)&g_O[row + tx * 8 + 4] = o1;
    }
}

// ---------------------------------------------------------------------------
extern "C" void kernel_launch(void* const* d_in, const int* in_sizes, int n_in,
                              void* d_out, int out_size)
{
    const float* x  = (const float*)d_in[0];
    const float* Wq = (const float*)d_in[1];
    const float* Wk = (const float*)d_in[2];
    const float* Wv = (const float*)d_in[3];
    const float* Wo = (const float*)d_in[4];
    float* out = (float*)d_out;

    const int flash_smem = FLASH_SMEM_FLOATS * (int)sizeof(float);
    cudaFuncSetAttribute(flash_kernel,
                         cudaFuncAttributeMaxDynamicSharedMemorySize, flash_smem);

    // Fused QKV projections: [8192,1024] @ [1024,128] x3 in one launch
    qkv_kernel<<<dim3(RR / 64, 1, 3), 256>>>(x, Wq, Wk, Wv);

    // Causal flash attention
    flash_kernel<<<dim3(TT / 64, BB), 512, flash_smem>>>();

    // Output projection: [8192,128] @ [128,1024]
    outproj_kernel<<<dim3(DD / 128, RR / 64), 256>>>(Wo, out);
}